// round 1
// baseline (speedup 1.0000x reference)
#include <cuda_runtime.h>

#define Hh 128
#define NS 18
#define PS 20   // padded stream count (float4-friendly)

// ---------------------------------------------------------------------------
// Truncated multivariate Taylor jet over monomials (normalized coefficients,
// c_a = d^a f / a!):
//  0:1  1:X 2:Y 3:T  4:X2 5:XY 6:Y2 7:XT 8:YT
//  9:X3 10:X2Y 11:XY2 12:Y3 13:X2T 14:Y2T  15:X4 16:X2Y2 17:Y4
// ---------------------------------------------------------------------------
__device__ __forceinline__ void tanh_jet(const float* __restrict__ u,
                                         float* __restrict__ o)
{
    const float t  = tanhf(u[0]);
    const float s  = 1.f - t * t;           // T1
    const float T2 = -t * s;
    const float T3 = (2.f * t * t - s) * s * (1.f / 3.f);
    const float T4 = (2.f * s - t * t) * t * s * (1.f / 3.f);

    const float a1 = u[1], a2 = u[2], a3 = u[3];
    const float b1 = u[4], b2 = u[5], b3 = u[6], b4 = u[7], b5 = u[8];
    const float c1 = u[9], c2 = u[10], c3 = u[11], c4 = u[12], c5 = u[13], c6 = u[14];
    const float d1 = u[15], d2 = u[16], d3 = u[17];

    const float a11 = a1 * a1, a22 = a2 * a2, a12 = a1 * a2;

    o[0] = t;
    o[1] = s * a1;
    o[2] = s * a2;
    o[3] = s * a3;
    // degree 2: T1*b + T2*(p^2)
    o[4] = s * b1 + T2 * a11;
    o[5] = s * b2 + T2 * (2.f * a12);
    o[6] = s * b3 + T2 * a22;
    o[7] = s * b4 + T2 * (2.f * a1 * a3);
    o[8] = s * b5 + T2 * (2.f * a2 * a3);
    // degree 3: T1*c + T2*(p^2) + T3*(p^3)
    o[9]  = s * c1 + T2 * (2.f * a1 * b1)             + T3 * (a11 * a1);
    o[10] = s * c2 + T2 * (2.f * (a1 * b2 + a2 * b1)) + T3 * (3.f * a11 * a2);
    o[11] = s * c3 + T2 * (2.f * (a1 * b3 + a2 * b2)) + T3 * (3.f * a1 * a22);
    o[12] = s * c4 + T2 * (2.f * a2 * b3)             + T3 * (a22 * a2);
    o[13] = s * c5 + T2 * (2.f * (a1 * b4 + a3 * b1)) + T3 * (3.f * a11 * a3);
    o[14] = s * c6 + T2 * (2.f * (a2 * b5 + a3 * b3)) + T3 * (3.f * a22 * a3);
    // degree 4: T1*d + T2*(p^2) + T3*(p^3) + T4*(p^4)
    o[15] = s * d1 + T2 * (2.f * a1 * c1 + b1 * b1)
                   + T3 * (3.f * a11 * b1)
                   + T4 * (a11 * a11);
    o[16] = s * d2 + T2 * (2.f * (a1 * c3 + a2 * c2 + b1 * b3) + b2 * b2)
                   + T3 * (3.f * (a11 * b3 + a22 * b1) + 6.f * a12 * b2)
                   + T4 * (6.f * a11 * a22);
    o[17] = s * d3 + T2 * (2.f * a2 * c4 + b3 * b3)
                   + T3 * (3.f * a22 * b3)
                   + T4 * (a22 * a22);
}

__device__ __forceinline__ void store_jets(float* __restrict__ jets, int j,
                                           const float* __restrict__ o)
{
    float4* wp = (float4*)(jets + j * PS);
    wp[0] = make_float4(o[0],  o[1],  o[2],  o[3]);
    wp[1] = make_float4(o[4],  o[5],  o[6],  o[7]);
    wp[2] = make_float4(o[8],  o[9],  o[10], o[11]);
    wp[3] = make_float4(o[12], o[13], o[14], o[15]);
    *(float2*)(jets + j * PS + 16) = make_float2(o[16], o[17]);
}

__device__ __forceinline__ void matvec(const float* __restrict__ Wsm,
                                       const float* __restrict__ jets,
                                       int j, float* __restrict__ acc)
{
#pragma unroll
    for (int s = 0; s < NS; ++s) acc[s] = 0.f;
#pragma unroll 4
    for (int i = 0; i < Hh; ++i) {
        const float w = Wsm[i * Hh + j];
        const float4* hp = (const float4*)(jets + i * PS);
        const float4 h0 = hp[0], h1 = hp[1], h2 = hp[2], h3 = hp[3];
        const float2 h4 = *(const float2*)(jets + i * PS + 16);
        acc[0]  = fmaf(w, h0.x, acc[0]);
        acc[1]  = fmaf(w, h0.y, acc[1]);
        acc[2]  = fmaf(w, h0.z, acc[2]);
        acc[3]  = fmaf(w, h0.w, acc[3]);
        acc[4]  = fmaf(w, h1.x, acc[4]);
        acc[5]  = fmaf(w, h1.y, acc[5]);
        acc[6]  = fmaf(w, h1.z, acc[6]);
        acc[7]  = fmaf(w, h1.w, acc[7]);
        acc[8]  = fmaf(w, h2.x, acc[8]);
        acc[9]  = fmaf(w, h2.y, acc[9]);
        acc[10] = fmaf(w, h2.z, acc[10]);
        acc[11] = fmaf(w, h2.w, acc[11]);
        acc[12] = fmaf(w, h3.x, acc[12]);
        acc[13] = fmaf(w, h3.y, acc[13]);
        acc[14] = fmaf(w, h3.z, acc[14]);
        acc[15] = fmaf(w, h3.w, acc[15]);
        acc[16] = fmaf(w, h4.x, acc[16]);
        acc[17] = fmaf(w, h4.y, acc[17]);
    }
}

__global__ void __launch_bounds__(256, 1)
hydro_kernel(const float* __restrict__ x,
             const float* __restrict__ W1, const float* __restrict__ b1,
             const float* __restrict__ W2, const float* __restrict__ b2,
             const float* __restrict__ W3, const float* __restrict__ b3,
             const float* __restrict__ W4, const float* __restrict__ b4,
             const float* __restrict__ nup,
             float* __restrict__ out, int N)
{
    extern __shared__ float sm[];
    float* Wsm2 = sm;                      // 128*128
    float* Wsm3 = sm + Hh * Hh;            // 128*128
    float* jets = Wsm3 + Hh * Hh;          // 2 * 128 * PS
    float* red  = jets + 2 * Hh * PS;      // 2 * 4 * NS

    const int tid     = threadIdx.x;
    const int slot    = tid >> 7;          // which of 2 samples in this CTA
    const int j       = tid & (Hh - 1);    // neuron index
    const int lane    = tid & 31;
    const int warpInS = (tid >> 5) & 3;

    // Stage weights into smem once per CTA (persistent CTAs).
    for (int k = tid; k < Hh * Hh; k += 256) {
        Wsm2[k] = W2[k];
        Wsm3[k] = W3[k];
    }
    __syncthreads();

    const float w1x = W1[j], w1y = W1[Hh + j], w1t = W1[2 * Hh + j];
    const float rb1 = b1[j], rb2 = b2[j], rb3 = b3[j], rw4 = W4[j];
    const float nu = nup[0];

    float* myjets = jets + slot * Hh * PS;
    float* myred  = red + slot * 4 * NS;

    const int npairs = N >> 1;
    for (int pair = blockIdx.x; pair < npairs; pair += gridDim.x) {
        const int n = 2 * pair + slot;
        const float px = x[3 * n], py = x[3 * n + 1], pt = x[3 * n + 2];

        float u[NS], o[NS];

        // ---- layer 1: pre-activation jet has only value + degree-1 terms
#pragma unroll
        for (int s = 0; s < NS; ++s) u[s] = 0.f;
        u[0] = fmaf(px, w1x, fmaf(py, w1y, fmaf(pt, w1t, rb1)));
        u[1] = w1x; u[2] = w1y; u[3] = w1t;
        tanh_jet(u, o);

        store_jets(myjets, j, o);
        __syncthreads();

        // ---- layer 2
        matvec(Wsm2, myjets, j, u);
        u[0] += rb2;
        __syncthreads();
        tanh_jet(u, o);
        store_jets(myjets, j, o);
        __syncthreads();

        // ---- layer 3
        matvec(Wsm3, myjets, j, u);
        u[0] += rb3;
        tanh_jet(u, o);

        // ---- layer 4: psi jet = sum_j o[j] * W4[j]  (warp reduce, then 4 warps)
#pragma unroll
        for (int s = 0; s < NS; ++s) {
            float v = o[s] * rw4;
            v += __shfl_xor_sync(0xffffffffu, v, 16);
            v += __shfl_xor_sync(0xffffffffu, v, 8);
            v += __shfl_xor_sync(0xffffffffu, v, 4);
            v += __shfl_xor_sync(0xffffffffu, v, 2);
            v += __shfl_xor_sync(0xffffffffu, v, 1);
            o[s] = v;
        }
        __syncthreads();   // previous iteration's red readers are done
        if (lane == 0) {
#pragma unroll
            for (int s = 0; s < NS; ++s) myred[warpInS * NS + s] = o[s];
        }
        __syncthreads();

        if (j == 0 && n < N) {
            float c[NS];
#pragma unroll
            for (int s = 0; s < NS; ++s)
                c[s] = myred[s] + myred[NS + s] + myred[2 * NS + s] + myred[3 * NS + s];

            // Convert normalized Taylor coefficients -> derivatives
            const float uu = c[2];            // psi_y
            const float vv = -c[1];           // -psi_x
            const float wx = -(6.f * c[9]  + 2.f * c[11]);   // -(psi_xxx + psi_xyy)
            const float wy = -(2.f * c[10] + 6.f * c[12]);   // -(psi_xxy + psi_yyy)
            const float wt = -(2.f * c[13] + 2.f * c[14]);   // -(psi_xxt + psi_yyt)
            const float lapw = -(24.f * c[15] + 8.f * c[16] + 24.f * c[17]);
            const float nse = wt + wx * uu + wy * vv - nu * lapw;

            out[2 * n]     = uu;
            out[2 * n + 1] = vv;
            out[2 * N + n] = nse;
        }
    }
}

extern "C" void kernel_launch(void* const* d_in, const int* in_sizes, int n_in,
                              void* d_out, int out_size)
{
    const float* x  = (const float*)d_in[0];
    const float* W1 = (const float*)d_in[1];
    const float* b1 = (const float*)d_in[2];
    const float* W2 = (const float*)d_in[3];
    const float* b2 = (const float*)d_in[4];
    const float* W3 = (const float*)d_in[5];
    const float* b3 = (const float*)d_in[6];
    const float* W4 = (const float*)d_in[7];
    const float* b4 = (const float*)d_in[8];
    const float* nu = (const float*)d_in[9];

    const int N = in_sizes[0] / 3;

    const size_t smem = (size_t)(2 * Hh * Hh + 2 * Hh * PS + 2 * 4 * NS) * sizeof(float);
    cudaFuncSetAttribute(hydro_kernel, cudaFuncAttributeMaxDynamicSharedMemorySize, (int)smem);

    int dev = 0, sms = 148;
    cudaGetDevice(&dev);
    cudaDeviceGetAttribute(&sms, cudaDevAttrMultiProcessorCount, dev);

    const int npairs = N >> 1;
    const int grid = npairs < sms ? npairs : sms;

    hydro_kernel<<<grid, 256, smem>>>(x, W1, b1, W2, b2, W3, b3, W4, b4, nu,
                                      (float*)d_out, N);
}

// round 2
// speedup vs baseline: 1.2883x; 1.2883x over previous
#include <cuda_runtime.h>

#define Hh 128
#define NS 18
#define PS 20      // padded stream count (16B-friendly: 80B row)
#define SLOTS 4    // samples per CTA

typedef unsigned long long u64;

// ---- packed fp32x2 helpers (sm_103a) --------------------------------------
__device__ __forceinline__ u64 ffma2(u64 a, u64 b, u64 c) {
    u64 d;
    asm("fma.rn.f32x2 %0, %1, %2, %3;" : "=l"(d) : "l"(a), "l"(b), "l"(c));
    return d;
}
__device__ __forceinline__ u64 splat2(float w) {
    u64 d; unsigned ui = __float_as_uint(w);
    asm("mov.b64 %0, {%1, %1};" : "=l"(d) : "r"(ui));
    return d;
}
__device__ __forceinline__ void unpack2(u64 v, float& lo, float& hi) {
    unsigned a, b;
    asm("mov.b64 {%0, %1}, %2;" : "=r"(a), "=r"(b) : "l"(v));
    lo = __uint_as_float(a); hi = __uint_as_float(b);
}

// ---------------------------------------------------------------------------
// Truncated multivariate Taylor jet over monomials (normalized coefficients):
//  0:1  1:X 2:Y 3:T  4:X2 5:XY 6:Y2 7:XT 8:YT
//  9:X3 10:X2Y 11:XY2 12:Y3 13:X2T 14:Y2T  15:X4 16:X2Y2 17:Y4
// ---------------------------------------------------------------------------
__device__ __forceinline__ void tanh_jet(const float* __restrict__ u,
                                         float* __restrict__ o)
{
    const float t  = tanhf(u[0]);
    const float s  = 1.f - t * t;           // T1
    const float T2 = -t * s;
    const float T3 = (2.f * t * t - s) * s * (1.f / 3.f);
    const float T4 = (2.f * s - t * t) * t * s * (1.f / 3.f);

    const float a1 = u[1], a2 = u[2], a3 = u[3];
    const float b1 = u[4], b2 = u[5], b3 = u[6], b4 = u[7], b5 = u[8];
    const float c1 = u[9], c2 = u[10], c3 = u[11], c4 = u[12], c5 = u[13], c6 = u[14];
    const float d1 = u[15], d2 = u[16], d3 = u[17];

    const float a11 = a1 * a1, a22 = a2 * a2, a12 = a1 * a2;

    o[0] = t;
    o[1] = s * a1;
    o[2] = s * a2;
    o[3] = s * a3;
    o[4] = s * b1 + T2 * a11;
    o[5] = s * b2 + T2 * (2.f * a12);
    o[6] = s * b3 + T2 * a22;
    o[7] = s * b4 + T2 * (2.f * a1 * a3);
    o[8] = s * b5 + T2 * (2.f * a2 * a3);
    o[9]  = s * c1 + T2 * (2.f * a1 * b1)             + T3 * (a11 * a1);
    o[10] = s * c2 + T2 * (2.f * (a1 * b2 + a2 * b1)) + T3 * (3.f * a11 * a2);
    o[11] = s * c3 + T2 * (2.f * (a1 * b3 + a2 * b2)) + T3 * (3.f * a1 * a22);
    o[12] = s * c4 + T2 * (2.f * a2 * b3)             + T3 * (a22 * a2);
    o[13] = s * c5 + T2 * (2.f * (a1 * b4 + a3 * b1)) + T3 * (3.f * a11 * a3);
    o[14] = s * c6 + T2 * (2.f * (a2 * b5 + a3 * b3)) + T3 * (3.f * a22 * a3);
    o[15] = s * d1 + T2 * (2.f * a1 * c1 + b1 * b1)
                   + T3 * (3.f * a11 * b1)
                   + T4 * (a11 * a11);
    o[16] = s * d2 + T2 * (2.f * (a1 * c3 + a2 * c2 + b1 * b3) + b2 * b2)
                   + T3 * (3.f * (a11 * b3 + a22 * b1) + 6.f * a12 * b2)
                   + T4 * (6.f * a11 * a22);
    o[17] = s * d3 + T2 * (2.f * a2 * c4 + b3 * b3)
                   + T3 * (3.f * a22 * b3)
                   + T4 * (a22 * a22);
}

__device__ __forceinline__ void store_jets(float* __restrict__ jets, int j,
                                           const float* __restrict__ o)
{
    float4* wp = (float4*)(jets + j * PS);
    wp[0] = make_float4(o[0],  o[1],  o[2],  o[3]);
    wp[1] = make_float4(o[4],  o[5],  o[6],  o[7]);
    wp[2] = make_float4(o[8],  o[9],  o[10], o[11]);
    wp[3] = make_float4(o[12], o[13], o[14], o[15]);
    *(float2*)(jets + j * PS + 16) = make_float2(o[16], o[17]);
}

// 2-neuron matvec with packed f32x2 FMAs. acc[0..8] = neuron j0 stream-pairs,
// acc[9..17] = neuron j0+64 stream-pairs.
__device__ __forceinline__ void matvec2(const float* __restrict__ Wsm,
                                        const float* __restrict__ jets,
                                        int j0, u64* __restrict__ acc)
{
#pragma unroll
    for (int s = 0; s < 18; ++s) acc[s] = 0ull;
#pragma unroll 2
    for (int i = 0; i < Hh; ++i) {
        const float* jrow = jets + i * PS;
        const ulonglong2* q = (const ulonglong2*)jrow;
        const ulonglong2 q0 = q[0], q1 = q[1], q2 = q[2], q3 = q[3];
        const u64 h8 = *(const u64*)(jrow + 16);
        const u64 w0 = splat2(Wsm[i * Hh + j0]);
        const u64 w1 = splat2(Wsm[i * Hh + j0 + 64]);
        acc[0]  = ffma2(w0, q0.x, acc[0]);
        acc[1]  = ffma2(w0, q0.y, acc[1]);
        acc[2]  = ffma2(w0, q1.x, acc[2]);
        acc[3]  = ffma2(w0, q1.y, acc[3]);
        acc[4]  = ffma2(w0, q2.x, acc[4]);
        acc[5]  = ffma2(w0, q2.y, acc[5]);
        acc[6]  = ffma2(w0, q3.x, acc[6]);
        acc[7]  = ffma2(w0, q3.y, acc[7]);
        acc[8]  = ffma2(w0, h8,   acc[8]);
        acc[9]  = ffma2(w1, q0.x, acc[9]);
        acc[10] = ffma2(w1, q0.y, acc[10]);
        acc[11] = ffma2(w1, q1.x, acc[11]);
        acc[12] = ffma2(w1, q1.y, acc[12]);
        acc[13] = ffma2(w1, q2.x, acc[13]);
        acc[14] = ffma2(w1, q2.y, acc[14]);
        acc[15] = ffma2(w1, q3.x, acc[15]);
        acc[16] = ffma2(w1, q3.y, acc[16]);
        acc[17] = ffma2(w1, h8,   acc[17]);
    }
}

__device__ __forceinline__ void unpack_accs(const u64* __restrict__ acc,
                                            float* __restrict__ u0,
                                            float* __restrict__ u1)
{
#pragma unroll
    for (int s = 0; s < 9; ++s) unpack2(acc[s],     u0[2 * s], u0[2 * s + 1]);
#pragma unroll
    for (int s = 0; s < 9; ++s) unpack2(acc[9 + s], u1[2 * s], u1[2 * s + 1]);
}

__global__ void __launch_bounds__(256, 1)
hydro_kernel(const float* __restrict__ x,
             const float* __restrict__ W1, const float* __restrict__ b1,
             const float* __restrict__ W2, const float* __restrict__ b2,
             const float* __restrict__ W3, const float* __restrict__ b3,
             const float* __restrict__ W4, const float* __restrict__ b4,
             const float* __restrict__ nup,
             float* __restrict__ out, int N)
{
    extern __shared__ float sm[];
    float* Wsm2 = sm;                           // 128*128
    float* Wsm3 = sm + Hh * Hh;                 // 128*128
    float* jets = Wsm3 + Hh * Hh;               // SLOTS * 128 * PS
    float* red  = jets + SLOTS * Hh * PS;       // SLOTS * 2 * NS

    const int tid   = threadIdx.x;
    const int slot  = tid >> 6;                 // sample slot 0..3
    const int jj    = tid & 63;                 // neuron pair index
    const int j0    = jj, j1 = jj + 64;
    const int warpInSlot = (tid >> 5) & 1;
    const int lane  = tid & 31;

    for (int k = tid; k < Hh * Hh; k += 256) {
        Wsm2[k] = W2[k];
        Wsm3[k] = W3[k];
    }
    __syncthreads();

    const float w1x0 = W1[j0],          w1x1 = W1[j1];
    const float w1y0 = W1[Hh + j0],     w1y1 = W1[Hh + j1];
    const float w1t0 = W1[2 * Hh + j0], w1t1 = W1[2 * Hh + j1];
    const float rb1_0 = b1[j0], rb1_1 = b1[j1];
    const float rb2_0 = b2[j0], rb2_1 = b2[j1];
    const float rb3_0 = b3[j0], rb3_1 = b3[j1];
    const float rw4_0 = W4[j0], rw4_1 = W4[j1];
    const float nu = nup[0];

    float* myjets = jets + slot * Hh * PS;
    float* myred  = red + slot * 2 * NS;

    const int ngroups = (N + SLOTS - 1) / SLOTS;
    for (int g = blockIdx.x; g < ngroups; g += gridDim.x) {
        const int n = SLOTS * g + slot;
        const bool active = (n < N);
        const int ni = active ? n : 0;
        const float px = x[3 * ni], py = x[3 * ni + 1], pt = x[3 * ni + 2];

        float u0[NS], u1[NS], o[NS], p[NS];
        u64 acc[18];

        // ---- layer 1 (degree <= 1 pre-activation jets), both neurons
#pragma unroll
        for (int s = 0; s < NS; ++s) u0[s] = 0.f;
        u0[0] = fmaf(px, w1x0, fmaf(py, w1y0, fmaf(pt, w1t0, rb1_0)));
        u0[1] = w1x0; u0[2] = w1y0; u0[3] = w1t0;
        tanh_jet(u0, o);
        store_jets(myjets, j0, o);

#pragma unroll
        for (int s = 0; s < NS; ++s) u0[s] = 0.f;
        u0[0] = fmaf(px, w1x1, fmaf(py, w1y1, fmaf(pt, w1t1, rb1_1)));
        u0[1] = w1x1; u0[2] = w1y1; u0[3] = w1t1;
        tanh_jet(u0, o);
        store_jets(myjets, j1, o);
        __syncthreads();

        // ---- layer 2
        matvec2(Wsm2, myjets, j0, acc);
        __syncthreads();                       // all reads done before overwrite
        unpack_accs(acc, u0, u1);
        u0[0] += rb2_0; u1[0] += rb2_1;
        tanh_jet(u0, o); store_jets(myjets, j0, o);
        tanh_jet(u1, o); store_jets(myjets, j1, o);
        __syncthreads();

        // ---- layer 3
        matvec2(Wsm3, myjets, j0, acc);
        unpack_accs(acc, u0, u1);
        u0[0] += rb3_0; u1[0] += rb3_1;

        tanh_jet(u0, o);
#pragma unroll
        for (int s = 0; s < NS; ++s) p[s] = o[s] * rw4_0;
        tanh_jet(u1, o);
#pragma unroll
        for (int s = 0; s < NS; ++s) p[s] = fmaf(o[s], rw4_1, p[s]);

        // ---- layer 4 reduction: warp-reduce, then 2 warps per slot via smem
#pragma unroll
        for (int s = 0; s < NS; ++s) {
            float v = p[s];
            v += __shfl_xor_sync(0xffffffffu, v, 16);
            v += __shfl_xor_sync(0xffffffffu, v, 8);
            v += __shfl_xor_sync(0xffffffffu, v, 4);
            v += __shfl_xor_sync(0xffffffffu, v, 2);
            v += __shfl_xor_sync(0xffffffffu, v, 1);
            p[s] = v;
        }
        if (lane == 0) {
#pragma unroll
            for (int s = 0; s < NS; ++s) myred[warpInSlot * NS + s] = p[s];
        }
        __syncthreads();

        if (jj == 0 && warpInSlot == 0 && active) {
            float c[NS];
#pragma unroll
            for (int s = 0; s < NS; ++s) c[s] = myred[s] + myred[NS + s];

            const float uu = c[2];                           // psi_y
            const float vv = -c[1];                          // -psi_x
            const float wx = -(6.f * c[9]  + 2.f * c[11]);   // -(psi_xxx + psi_xyy)
            const float wy = -(2.f * c[10] + 6.f * c[12]);   // -(psi_xxy + psi_yyy)
            const float wt = -(2.f * c[13] + 2.f * c[14]);   // -(psi_xxt + psi_yyt)
            const float lapw = -(24.f * c[15] + 8.f * c[16] + 24.f * c[17]);
            const float nse = wt + wx * uu + wy * vv - nu * lapw;

            out[2 * n]     = uu;
            out[2 * n + 1] = vv;
            out[2 * N + n] = nse;
        }
        __syncthreads();   // red consumed before next iteration rewrites it
    }
}

extern "C" void kernel_launch(void* const* d_in, const int* in_sizes, int n_in,
                              void* d_out, int out_size)
{
    const float* x  = (const float*)d_in[0];
    const float* W1 = (const float*)d_in[1];
    const float* b1 = (const float*)d_in[2];
    const float* W2 = (const float*)d_in[3];
    const float* b2 = (const float*)d_in[4];
    const float* W3 = (const float*)d_in[5];
    const float* b3 = (const float*)d_in[6];
    const float* W4 = (const float*)d_in[7];
    const float* b4 = (const float*)d_in[8];
    const float* nu = (const float*)d_in[9];

    const int N = in_sizes[0] / 3;

    const size_t smem = (size_t)(2 * Hh * Hh + SLOTS * Hh * PS + SLOTS * 2 * NS)
                        * sizeof(float);
    cudaFuncSetAttribute(hydro_kernel, cudaFuncAttributeMaxDynamicSharedMemorySize,
                         (int)smem);

    int dev = 0, sms = 148;
    cudaGetDevice(&dev);
    cudaDeviceGetAttribute(&sms, cudaDevAttrMultiProcessorCount, dev);

    const int ngroups = (N + SLOTS - 1) / SLOTS;
    const int grid = ngroups < sms ? ngroups : sms;

    hydro_kernel<<<grid, 256, smem>>>(x, W1, b1, W2, b2, W3, b3, W4, b4, nu,
                                      (float*)d_out, N);
}

// round 3
// speedup vs baseline: 1.4911x; 1.1574x over previous
#include <cuda_runtime.h>

#define Hh 128
#define NS 18
#define PS 20      // padded stream count (16B-friendly: 80B row)
#define SLOTS 6    // samples per CTA
#define NTHREADS (SLOTS * 64)

typedef unsigned long long u64;

// ---- packed fp32x2 helpers (sm_103a) --------------------------------------
__device__ __forceinline__ u64 ffma2(u64 a, u64 b, u64 c) {
    u64 d;
    asm("fma.rn.f32x2 %0, %1, %2, %3;" : "=l"(d) : "l"(a), "l"(b), "l"(c));
    return d;
}
__device__ __forceinline__ u64 splat2(float w) {
    u64 d; unsigned ui = __float_as_uint(w);
    asm("mov.b64 %0, {%1, %1};" : "=l"(d) : "r"(ui));
    return d;
}
__device__ __forceinline__ void unpack2(u64 v, float& lo, float& hi) {
    unsigned a, b;
    asm("mov.b64 {%0, %1}, %2;" : "=r"(a), "=r"(b) : "l"(v));
    lo = __uint_as_float(a); hi = __uint_as_float(b);
}

// ---------------------------------------------------------------------------
// Truncated multivariate Taylor jet over monomials (normalized coefficients):
//  0:1  1:X 2:Y 3:T  4:X2 5:XY 6:Y2 7:XT 8:YT
//  9:X3 10:X2Y 11:XY2 12:Y3 13:X2T 14:Y2T  15:X4 16:X2Y2 17:Y4
// ---------------------------------------------------------------------------
__device__ __forceinline__ void tanh_jet(const float* __restrict__ u,
                                         float* __restrict__ o)
{
    const float t  = tanhf(u[0]);
    const float s  = 1.f - t * t;           // T1
    const float T2 = -t * s;
    const float T3 = (2.f * t * t - s) * s * (1.f / 3.f);
    const float T4 = (2.f * s - t * t) * t * s * (1.f / 3.f);

    const float a1 = u[1], a2 = u[2], a3 = u[3];
    const float b1 = u[4], b2 = u[5], b3 = u[6], b4 = u[7], b5 = u[8];
    const float c1 = u[9], c2 = u[10], c3 = u[11], c4 = u[12], c5 = u[13], c6 = u[14];
    const float d1 = u[15], d2 = u[16], d3 = u[17];

    const float a11 = a1 * a1, a22 = a2 * a2, a12 = a1 * a2;

    o[0] = t;
    o[1] = s * a1;
    o[2] = s * a2;
    o[3] = s * a3;
    o[4] = s * b1 + T2 * a11;
    o[5] = s * b2 + T2 * (2.f * a12);
    o[6] = s * b3 + T2 * a22;
    o[7] = s * b4 + T2 * (2.f * a1 * a3);
    o[8] = s * b5 + T2 * (2.f * a2 * a3);
    o[9]  = s * c1 + T2 * (2.f * a1 * b1)             + T3 * (a11 * a1);
    o[10] = s * c2 + T2 * (2.f * (a1 * b2 + a2 * b1)) + T3 * (3.f * a11 * a2);
    o[11] = s * c3 + T2 * (2.f * (a1 * b3 + a2 * b2)) + T3 * (3.f * a1 * a22);
    o[12] = s * c4 + T2 * (2.f * a2 * b3)             + T3 * (a22 * a2);
    o[13] = s * c5 + T2 * (2.f * (a1 * b4 + a3 * b1)) + T3 * (3.f * a11 * a3);
    o[14] = s * c6 + T2 * (2.f * (a2 * b5 + a3 * b3)) + T3 * (3.f * a22 * a3);
    o[15] = s * d1 + T2 * (2.f * a1 * c1 + b1 * b1)
                   + T3 * (3.f * a11 * b1)
                   + T4 * (a11 * a11);
    o[16] = s * d2 + T2 * (2.f * (a1 * c3 + a2 * c2 + b1 * b3) + b2 * b2)
                   + T3 * (3.f * (a11 * b3 + a22 * b1) + 6.f * a12 * b2)
                   + T4 * (6.f * a11 * a22);
    o[17] = s * d3 + T2 * (2.f * a2 * c4 + b3 * b3)
                   + T3 * (3.f * a22 * b3)
                   + T4 * (a22 * a22);
}

__device__ __forceinline__ void store_jets(float* __restrict__ jets, int j,
                                           const float* __restrict__ o)
{
    float4* wp = (float4*)(jets + j * PS);
    wp[0] = make_float4(o[0],  o[1],  o[2],  o[3]);
    wp[1] = make_float4(o[4],  o[5],  o[6],  o[7]);
    wp[2] = make_float4(o[8],  o[9],  o[10], o[11]);
    wp[3] = make_float4(o[12], o[13], o[14], o[15]);
    *(float2*)(jets + j * PS + 16) = make_float2(o[16], o[17]);
}

// 2-neuron matvec with packed f32x2 FMAs. acc[0..8] = neuron j0 stream-pairs,
// acc[9..17] = neuron j0+64 stream-pairs.
__device__ __forceinline__ void matvec2(const float* __restrict__ Wsm,
                                        const float* __restrict__ jets,
                                        int j0, u64* __restrict__ acc)
{
#pragma unroll
    for (int s = 0; s < 18; ++s) acc[s] = 0ull;
#pragma unroll 2
    for (int i = 0; i < Hh; ++i) {
        const float* jrow = jets + i * PS;
        const ulonglong2* q = (const ulonglong2*)jrow;
        const ulonglong2 q0 = q[0], q1 = q[1], q2 = q[2], q3 = q[3];
        const u64 h8 = *(const u64*)(jrow + 16);
        const u64 w0 = splat2(Wsm[i * Hh + j0]);
        const u64 w1 = splat2(Wsm[i * Hh + j0 + 64]);
        acc[0]  = ffma2(w0, q0.x, acc[0]);
        acc[1]  = ffma2(w0, q0.y, acc[1]);
        acc[2]  = ffma2(w0, q1.x, acc[2]);
        acc[3]  = ffma2(w0, q1.y, acc[3]);
        acc[4]  = ffma2(w0, q2.x, acc[4]);
        acc[5]  = ffma2(w0, q2.y, acc[5]);
        acc[6]  = ffma2(w0, q3.x, acc[6]);
        acc[7]  = ffma2(w0, q3.y, acc[7]);
        acc[8]  = ffma2(w0, h8,   acc[8]);
        acc[9]  = ffma2(w1, q0.x, acc[9]);
        acc[10] = ffma2(w1, q0.y, acc[10]);
        acc[11] = ffma2(w1, q1.x, acc[11]);
        acc[12] = ffma2(w1, q1.y, acc[12]);
        acc[13] = ffma2(w1, q2.x, acc[13]);
        acc[14] = ffma2(w1, q2.y, acc[14]);
        acc[15] = ffma2(w1, q3.x, acc[15]);
        acc[16] = ffma2(w1, q3.y, acc[16]);
        acc[17] = ffma2(w1, h8,   acc[17]);
    }
}

__device__ __forceinline__ void unpack_accs(const u64* __restrict__ acc,
                                            float* __restrict__ u0,
                                            float* __restrict__ u1)
{
#pragma unroll
    for (int s = 0; s < 9; ++s) unpack2(acc[s],     u0[2 * s], u0[2 * s + 1]);
#pragma unroll
    for (int s = 0; s < 9; ++s) unpack2(acc[9 + s], u1[2 * s], u1[2 * s + 1]);
}

__global__ void __launch_bounds__(NTHREADS, 1)
hydro_kernel(const float* __restrict__ x,
             const float* __restrict__ W1, const float* __restrict__ b1,
             const float* __restrict__ W2, const float* __restrict__ b2,
             const float* __restrict__ W3, const float* __restrict__ b3,
             const float* __restrict__ W4, const float* __restrict__ b4,
             const float* __restrict__ nup,
             float* __restrict__ out, int N)
{
    extern __shared__ float sm[];
    float* Wsm2 = sm;                           // 128*128
    float* Wsm3 = sm + Hh * Hh;                 // 128*128
    float* jets = Wsm3 + Hh * Hh;               // SLOTS * 128 * PS
    float* red  = jets + SLOTS * Hh * PS;       // SLOTS * 2 * NS

    const int tid   = threadIdx.x;
    const int slot  = tid >> 6;                 // sample slot 0..SLOTS-1
    const int jj    = tid & 63;                 // neuron pair index
    const int j0    = jj, j1 = jj + 64;
    const int warpInSlot = (tid >> 5) & 1;
    const int lane  = tid & 31;

    for (int k = tid; k < Hh * Hh; k += NTHREADS) {
        Wsm2[k] = W2[k];
        Wsm3[k] = W3[k];
    }
    __syncthreads();

    const float w1x0 = W1[j0],          w1x1 = W1[j1];
    const float w1y0 = W1[Hh + j0],     w1y1 = W1[Hh + j1];
    const float w1t0 = W1[2 * Hh + j0], w1t1 = W1[2 * Hh + j1];
    const float rb1_0 = b1[j0], rb1_1 = b1[j1];
    const float rb2_0 = b2[j0], rb2_1 = b2[j1];
    const float rb3_0 = b3[j0], rb3_1 = b3[j1];
    const float rw4_0 = W4[j0], rw4_1 = W4[j1];
    const float nu = nup[0];

    float* myjets = jets + slot * Hh * PS;
    float* myred  = red + slot * 2 * NS;

    const int ngroups = (N + SLOTS - 1) / SLOTS;
    for (int g = blockIdx.x; g < ngroups; g += gridDim.x) {
        const int n = SLOTS * g + slot;
        const bool active = (n < N);
        const int ni = active ? n : 0;
        const float px = x[3 * ni], py = x[3 * ni + 1], pt = x[3 * ni + 2];

        float u0[NS], u1[NS], o[NS], p[NS];
        u64 acc[18];

        // ---- layer 1 (degree <= 1 pre-activation jets), both neurons
#pragma unroll
        for (int s = 0; s < NS; ++s) u0[s] = 0.f;
        u0[0] = fmaf(px, w1x0, fmaf(py, w1y0, fmaf(pt, w1t0, rb1_0)));
        u0[1] = w1x0; u0[2] = w1y0; u0[3] = w1t0;
        tanh_jet(u0, o);
        store_jets(myjets, j0, o);

#pragma unroll
        for (int s = 0; s < NS; ++s) u0[s] = 0.f;
        u0[0] = fmaf(px, w1x1, fmaf(py, w1y1, fmaf(pt, w1t1, rb1_1)));
        u0[1] = w1x1; u0[2] = w1y1; u0[3] = w1t1;
        tanh_jet(u0, o);
        store_jets(myjets, j1, o);
        __syncthreads();

        // ---- layer 2
        matvec2(Wsm2, myjets, j0, acc);
        __syncthreads();                       // all reads done before overwrite
        unpack_accs(acc, u0, u1);
        u0[0] += rb2_0; u1[0] += rb2_1;
        tanh_jet(u0, o); store_jets(myjets, j0, o);
        tanh_jet(u1, o); store_jets(myjets, j1, o);
        __syncthreads();

        // ---- layer 3
        matvec2(Wsm3, myjets, j0, acc);
        unpack_accs(acc, u0, u1);
        u0[0] += rb3_0; u1[0] += rb3_1;

        tanh_jet(u0, o);
#pragma unroll
        for (int s = 0; s < NS; ++s) p[s] = o[s] * rw4_0;
        tanh_jet(u1, o);
#pragma unroll
        for (int s = 0; s < NS; ++s) p[s] = fmaf(o[s], rw4_1, p[s]);

        // ---- layer 4 reduction: warp-reduce, then 2 warps per slot via smem
#pragma unroll
        for (int s = 0; s < NS; ++s) {
            float v = p[s];
            v += __shfl_xor_sync(0xffffffffu, v, 16);
            v += __shfl_xor_sync(0xffffffffu, v, 8);
            v += __shfl_xor_sync(0xffffffffu, v, 4);
            v += __shfl_xor_sync(0xffffffffu, v, 2);
            v += __shfl_xor_sync(0xffffffffu, v, 1);
            p[s] = v;
        }
        if (lane == 0) {
#pragma unroll
            for (int s = 0; s < NS; ++s) myred[warpInSlot * NS + s] = p[s];
        }
        __syncthreads();

        if (jj == 0 && warpInSlot == 0 && active) {
            float c[NS];
#pragma unroll
            for (int s = 0; s < NS; ++s) c[s] = myred[s] + myred[NS + s];

            const float uu = c[2];                           // psi_y
            const float vv = -c[1];                          // -psi_x
            const float wx = -(6.f * c[9]  + 2.f * c[11]);   // -(psi_xxx + psi_xyy)
            const float wy = -(2.f * c[10] + 6.f * c[12]);   // -(psi_xxy + psi_yyy)
            const float wt = -(2.f * c[13] + 2.f * c[14]);   // -(psi_xxt + psi_yyt)
            const float lapw = -(24.f * c[15] + 8.f * c[16] + 24.f * c[17]);
            const float nse = wt + wx * uu + wy * vv - nu * lapw;

            out[2 * n]     = uu;
            out[2 * n + 1] = vv;
            out[2 * N + n] = nse;
        }
        __syncthreads();   // red consumed before next iteration rewrites it
    }
}

extern "C" void kernel_launch(void* const* d_in, const int* in_sizes, int n_in,
                              void* d_out, int out_size)
{
    const float* x  = (const float*)d_in[0];
    const float* W1 = (const float*)d_in[1];
    const float* b1 = (const float*)d_in[2];
    const float* W2 = (const float*)d_in[3];
    const float* b2 = (const float*)d_in[4];
    const float* W3 = (const float*)d_in[5];
    const float* b3 = (const float*)d_in[6];
    const float* W4 = (const float*)d_in[7];
    const float* b4 = (const float*)d_in[8];
    const float* nu = (const float*)d_in[9];

    const int N = in_sizes[0] / 3;

    const size_t smem = (size_t)(2 * Hh * Hh + SLOTS * Hh * PS + SLOTS * 2 * NS)
                        * sizeof(float);
    cudaFuncSetAttribute(hydro_kernel, cudaFuncAttributeMaxDynamicSharedMemorySize,
                         (int)smem);

    int dev = 0, sms = 148;
    cudaGetDevice(&dev);
    cudaDeviceGetAttribute(&sms, cudaDevAttrMultiProcessorCount, dev);

    const int ngroups = (N + SLOTS - 1) / SLOTS;
    const int grid = ngroups < sms ? ngroups : sms;

    hydro_kernel<<<grid, NTHREADS, smem>>>(x, W1, b1, W2, b2, W3, b3, W4, b4, nu,
                                           (float*)d_out, N);
}

// round 4
// speedup vs baseline: 1.8201x; 1.2206x over previous
#include <cuda_runtime.h>

#define Hh 128
#define NS 18
#define PS 20      // padded stream count (16B-friendly: 80B row)
#define SLOTS 8    // samples per CTA
#define NTHREADS (SLOTS * 64)

typedef unsigned long long u64;

// ---- packed fp32x2 helpers (sm_103a) --------------------------------------
__device__ __forceinline__ u64 ffma2(u64 a, u64 b, u64 c) {
    u64 d;
    asm("fma.rn.f32x2 %0, %1, %2, %3;" : "=l"(d) : "l"(a), "l"(b), "l"(c));
    return d;
}
__device__ __forceinline__ u64 splat2(float w) {
    u64 d; unsigned ui = __float_as_uint(w);
    asm("mov.b64 %0, {%1, %1};" : "=l"(d) : "r"(ui));
    return d;
}
__device__ __forceinline__ void unpack2(u64 v, float& lo, float& hi) {
    unsigned a, b;
    asm("mov.b64 {%0, %1}, %2;" : "=r"(a), "=r"(b) : "l"(v));
    lo = __uint_as_float(a); hi = __uint_as_float(b);
}

// slot-local named barrier: 2 warps (64 threads) of one sample slot
__device__ __forceinline__ void slot_bar(int id) {
    asm volatile("bar.sync %0, 64;" :: "r"(id) : "memory");
}

// ---------------------------------------------------------------------------
// Truncated multivariate Taylor jet over monomials (normalized coefficients):
//  0:1  1:X 2:Y 3:T  4:X2 5:XY 6:Y2 7:XT 8:YT
//  9:X3 10:X2Y 11:XY2 12:Y3 13:X2T 14:Y2T  15:X4 16:X2Y2 17:Y4
// ---------------------------------------------------------------------------
__device__ __forceinline__ void tanh_jet(const float* __restrict__ u,
                                         float* __restrict__ o)
{
    const float t  = tanhf(u[0]);
    const float s  = 1.f - t * t;           // T1
    const float T2 = -t * s;
    const float T3 = (2.f * t * t - s) * s * (1.f / 3.f);
    const float T4 = (2.f * s - t * t) * t * s * (1.f / 3.f);

    const float a1 = u[1], a2 = u[2], a3 = u[3];
    const float b1 = u[4], b2 = u[5], b3 = u[6], b4 = u[7], b5 = u[8];
    const float c1 = u[9], c2 = u[10], c3 = u[11], c4 = u[12], c5 = u[13], c6 = u[14];
    const float d1 = u[15], d2 = u[16], d3 = u[17];

    const float a11 = a1 * a1, a22 = a2 * a2, a12 = a1 * a2;

    o[0] = t;
    o[1] = s * a1;
    o[2] = s * a2;
    o[3] = s * a3;
    o[4] = s * b1 + T2 * a11;
    o[5] = s * b2 + T2 * (2.f * a12);
    o[6] = s * b3 + T2 * a22;
    o[7] = s * b4 + T2 * (2.f * a1 * a3);
    o[8] = s * b5 + T2 * (2.f * a2 * a3);
    o[9]  = s * c1 + T2 * (2.f * a1 * b1)             + T3 * (a11 * a1);
    o[10] = s * c2 + T2 * (2.f * (a1 * b2 + a2 * b1)) + T3 * (3.f * a11 * a2);
    o[11] = s * c3 + T2 * (2.f * (a1 * b3 + a2 * b2)) + T3 * (3.f * a1 * a22);
    o[12] = s * c4 + T2 * (2.f * a2 * b3)             + T3 * (a22 * a2);
    o[13] = s * c5 + T2 * (2.f * (a1 * b4 + a3 * b1)) + T3 * (3.f * a11 * a3);
    o[14] = s * c6 + T2 * (2.f * (a2 * b5 + a3 * b3)) + T3 * (3.f * a22 * a3);
    o[15] = s * d1 + T2 * (2.f * a1 * c1 + b1 * b1)
                   + T3 * (3.f * a11 * b1)
                   + T4 * (a11 * a11);
    o[16] = s * d2 + T2 * (2.f * (a1 * c3 + a2 * c2 + b1 * b3) + b2 * b2)
                   + T3 * (3.f * (a11 * b3 + a22 * b1) + 6.f * a12 * b2)
                   + T4 * (6.f * a11 * a22);
    o[17] = s * d3 + T2 * (2.f * a2 * c4 + b3 * b3)
                   + T3 * (3.f * a22 * b3)
                   + T4 * (a22 * a22);
}

__device__ __forceinline__ void store_jets(float* __restrict__ jets, int j,
                                           const float* __restrict__ o)
{
    float4* wp = (float4*)(jets + j * PS);
    wp[0] = make_float4(o[0],  o[1],  o[2],  o[3]);
    wp[1] = make_float4(o[4],  o[5],  o[6],  o[7]);
    wp[2] = make_float4(o[8],  o[9],  o[10], o[11]);
    wp[3] = make_float4(o[12], o[13], o[14], o[15]);
    *(float2*)(jets + j * PS + 16) = make_float2(o[16], o[17]);
}

// 2-neuron matvec with packed f32x2 FMAs. Weights pre-interleaved in smem as
// float2 pairs (W[i][jj], W[i][jj+64]). acc[0..8] = neuron jj stream-pairs,
// acc[9..17] = neuron jj+64 stream-pairs.
__device__ __forceinline__ void matvec2(const float2* __restrict__ Wp,
                                        const float* __restrict__ jets,
                                        int jj, u64* __restrict__ acc)
{
#pragma unroll
    for (int s = 0; s < 18; ++s) acc[s] = 0ull;
#pragma unroll 4
    for (int i = 0; i < Hh; ++i) {
        const float* jrow = jets + i * PS;
        const ulonglong2* q = (const ulonglong2*)jrow;
        const ulonglong2 q0 = q[0], q1 = q[1], q2 = q[2], q3 = q[3];
        const u64 h8 = *(const u64*)(jrow + 16);
        const float2 w01 = Wp[i * 64 + jj];
        const u64 w0 = splat2(w01.x);
        const u64 w1 = splat2(w01.y);
        acc[0]  = ffma2(w0, q0.x, acc[0]);
        acc[1]  = ffma2(w0, q0.y, acc[1]);
        acc[2]  = ffma2(w0, q1.x, acc[2]);
        acc[3]  = ffma2(w0, q1.y, acc[3]);
        acc[4]  = ffma2(w0, q2.x, acc[4]);
        acc[5]  = ffma2(w0, q2.y, acc[5]);
        acc[6]  = ffma2(w0, q3.x, acc[6]);
        acc[7]  = ffma2(w0, q3.y, acc[7]);
        acc[8]  = ffma2(w0, h8,   acc[8]);
        acc[9]  = ffma2(w1, q0.x, acc[9]);
        acc[10] = ffma2(w1, q0.y, acc[10]);
        acc[11] = ffma2(w1, q1.x, acc[11]);
        acc[12] = ffma2(w1, q1.y, acc[12]);
        acc[13] = ffma2(w1, q2.x, acc[13]);
        acc[14] = ffma2(w1, q2.y, acc[14]);
        acc[15] = ffma2(w1, q3.x, acc[15]);
        acc[16] = ffma2(w1, q3.y, acc[16]);
        acc[17] = ffma2(w1, h8,   acc[17]);
    }
}

__global__ void __launch_bounds__(NTHREADS, 1)
hydro_kernel(const float* __restrict__ x,
             const float* __restrict__ W1, const float* __restrict__ b1,
             const float* __restrict__ W2, const float* __restrict__ b2,
             const float* __restrict__ W3, const float* __restrict__ b3,
             const float* __restrict__ W4, const float* __restrict__ b4,
             const float* __restrict__ nup,
             float* __restrict__ out, int N)
{
    extern __shared__ float sm[];
    float2* Wp2 = (float2*)sm;                      // 128*64 float2
    float2* Wp3 = Wp2 + Hh * 64;                    // 128*64 float2
    float* jets = (float*)(Wp3 + Hh * 64);          // SLOTS * 128 * PS
    float* red  = jets + SLOTS * Hh * PS;           // SLOTS * 2 * NS

    const int tid   = threadIdx.x;
    const int slot  = tid >> 6;                 // sample slot 0..SLOTS-1
    const int jj    = tid & 63;                 // neuron pair index
    const int j0    = jj, j1 = jj + 64;
    const int warpInSlot = (tid >> 5) & 1;
    const int lane  = tid & 31;
    const int barid = slot + 1;

    // Stage weights interleaved: Wp[i*64+jj] = (W[i*128+jj], W[i*128+jj+64])
    for (int k = tid; k < Hh * 64; k += NTHREADS) {
        const int i = k >> 6, c = k & 63;
        Wp2[k] = make_float2(W2[i * Hh + c], W2[i * Hh + c + 64]);
        Wp3[k] = make_float2(W3[i * Hh + c], W3[i * Hh + c + 64]);
    }
    __syncthreads();

    const float w1x0 = W1[j0],          w1x1 = W1[j1];
    const float w1y0 = W1[Hh + j0],     w1y1 = W1[Hh + j1];
    const float w1t0 = W1[2 * Hh + j0], w1t1 = W1[2 * Hh + j1];
    const float rb1_0 = b1[j0], rb1_1 = b1[j1];
    const float rb2_0 = b2[j0], rb2_1 = b2[j1];
    const float rb3_0 = b3[j0], rb3_1 = b3[j1];
    const float rw4_0 = W4[j0], rw4_1 = W4[j1];
    const float nu = nup[0];

    float* myjets = jets + slot * Hh * PS;
    float* myred  = red + slot * 2 * NS;

    const int ngroups = (N + SLOTS - 1) / SLOTS;
    for (int g = blockIdx.x; g < ngroups; g += gridDim.x) {
        const int n = SLOTS * g + slot;
        const bool active = (n < N);
        const int ni = active ? n : 0;
        const float px = x[3 * ni], py = x[3 * ni + 1], pt = x[3 * ni + 2];

        float u[NS], o[NS], p[NS];
        u64 acc[18];

        // ---- layer 1 (degree <= 1 pre-activation jets), both neurons
#pragma unroll
        for (int s = 0; s < NS; ++s) u[s] = 0.f;
        u[0] = fmaf(px, w1x0, fmaf(py, w1y0, fmaf(pt, w1t0, rb1_0)));
        u[1] = w1x0; u[2] = w1y0; u[3] = w1t0;
        tanh_jet(u, o);
        store_jets(myjets, j0, o);

#pragma unroll
        for (int s = 0; s < NS; ++s) u[s] = 0.f;
        u[0] = fmaf(px, w1x1, fmaf(py, w1y1, fmaf(pt, w1t1, rb1_1)));
        u[1] = w1x1; u[2] = w1y1; u[3] = w1t1;
        tanh_jet(u, o);
        store_jets(myjets, j1, o);
        slot_bar(barid);

        // ---- layer 2
        matvec2(Wp2, myjets, jj, acc);
        slot_bar(barid);                   // all slot reads done before overwrite
        // neuron j0
#pragma unroll
        for (int s = 0; s < 9; ++s) unpack2(acc[s], u[2 * s], u[2 * s + 1]);
        u[0] += rb2_0;
        tanh_jet(u, o); store_jets(myjets, j0, o);
        // neuron j1
#pragma unroll
        for (int s = 0; s < 9; ++s) unpack2(acc[9 + s], u[2 * s], u[2 * s + 1]);
        u[0] += rb2_1;
        tanh_jet(u, o); store_jets(myjets, j1, o);
        slot_bar(barid);

        // ---- layer 3
        matvec2(Wp3, myjets, jj, acc);
        // neuron j0
#pragma unroll
        for (int s = 0; s < 9; ++s) unpack2(acc[s], u[2 * s], u[2 * s + 1]);
        u[0] += rb3_0;
        tanh_jet(u, o);
#pragma unroll
        for (int s = 0; s < NS; ++s) p[s] = o[s] * rw4_0;
        // neuron j1
#pragma unroll
        for (int s = 0; s < 9; ++s) unpack2(acc[9 + s], u[2 * s], u[2 * s + 1]);
        u[0] += rb3_1;
        tanh_jet(u, o);
#pragma unroll
        for (int s = 0; s < NS; ++s) p[s] = fmaf(o[s], rw4_1, p[s]);

        // ---- layer 4 reduction: warp-reduce, then 2 warps per slot via smem
#pragma unroll
        for (int s = 0; s < NS; ++s) {
            float v = p[s];
            v += __shfl_xor_sync(0xffffffffu, v, 16);
            v += __shfl_xor_sync(0xffffffffu, v, 8);
            v += __shfl_xor_sync(0xffffffffu, v, 4);
            v += __shfl_xor_sync(0xffffffffu, v, 2);
            v += __shfl_xor_sync(0xffffffffu, v, 1);
            p[s] = v;
        }
        if (lane == 0) {
#pragma unroll
            for (int s = 0; s < NS; ++s) myred[warpInSlot * NS + s] = p[s];
        }
        slot_bar(barid);

        if (jj == 0 && warpInSlot == 0 && active) {
            float c[NS];
#pragma unroll
            for (int s = 0; s < NS; ++s) c[s] = myred[s] + myred[NS + s];

            const float uu = c[2];                           // psi_y
            const float vv = -c[1];                          // -psi_x
            const float wx = -(6.f * c[9]  + 2.f * c[11]);   // -(psi_xxx + psi_xyy)
            const float wy = -(2.f * c[10] + 6.f * c[12]);   // -(psi_xxy + psi_yyy)
            const float wt = -(2.f * c[13] + 2.f * c[14]);   // -(psi_xxt + psi_yyt)
            const float lapw = -(24.f * c[15] + 8.f * c[16] + 24.f * c[17]);
            const float nse = wt + wx * uu + wy * vv - nu * lapw;

            out[2 * n]     = uu;
            out[2 * n + 1] = vv;
            out[2 * N + n] = nse;
        }
        slot_bar(barid);   // red consumed before next iteration rewrites it
    }
}

extern "C" void kernel_launch(void* const* d_in, const int* in_sizes, int n_in,
                              void* d_out, int out_size)
{
    const float* x  = (const float*)d_in[0];
    const float* W1 = (const float*)d_in[1];
    const float* b1 = (const float*)d_in[2];
    const float* W2 = (const float*)d_in[3];
    const float* b2 = (const float*)d_in[4];
    const float* W3 = (const float*)d_in[5];
    const float* b3 = (const float*)d_in[6];
    const float* W4 = (const float*)d_in[7];
    const float* b4 = (const float*)d_in[8];
    const float* nu = (const float*)d_in[9];

    const int N = in_sizes[0] / 3;

    const size_t smem = (size_t)(2 * Hh * Hh + SLOTS * Hh * PS + SLOTS * 2 * NS)
                        * sizeof(float);
    cudaFuncSetAttribute(hydro_kernel, cudaFuncAttributeMaxDynamicSharedMemorySize,
                         (int)smem);

    int dev = 0, sms = 148;
    cudaGetDevice(&dev);
    cudaDeviceGetAttribute(&sms, cudaDevAttrMultiProcessorCount, dev);

    const int ngroups = (N + SLOTS - 1) / SLOTS;
    const int grid = ngroups < sms ? ngroups : sms;

    hydro_kernel<<<grid, NTHREADS, smem>>>(x, W1, b1, W2, b2, W3, b3, W4, b4, nu,
                                           (float*)d_out, N);
}